// round 1
// baseline (speedup 1.0000x reference)
#include <cuda_runtime.h>
#include <math.h>

// Problem constants (fixed shapes)
#define Tn   4096          // tokens = B*C
#define Dm   1024          // model dim
#define Hm   4096          // hidden dim (4*d)
#define NE   8             // experts
#define CAP  1280          // capacity = floor(2*1.25*4096/8), already even
#define BM   128
#define BN   128
#define BK   16

typedef unsigned long long u64;

// ---------------- scratch (device globals; no allocations allowed) ----------
__device__ int   g_e0[Tn], g_e1[Tn];
__device__ float g_w0[Tn], g_w1[Tn];
__device__ int   g_s0[Tn], g_s1[Tn];
__device__ int   g_tok[NE * CAP];
__device__ int   g_count[NE];
__device__ float g_h [(size_t)NE * CAP * Hm];   // expert hidden (gelu output)
__device__ float g_eo[(size_t)NE * CAP * Dm];   // expert output

// ---------------- packed f32x2 helpers (Blackwell) ---------------------------
__device__ __forceinline__ u64 pack2(float lo, float hi) {
    u64 r; asm("mov.b64 %0, {%1,%2};" : "=l"(r) : "f"(lo), "f"(hi)); return r;
}
__device__ __forceinline__ void unpack2(u64 v, float &lo, float &hi) {
    asm("mov.b64 {%0,%1}, %2;" : "=f"(lo), "=f"(hi) : "l"(v));
}
__device__ __forceinline__ u64 fma2(u64 a, u64 b, u64 c) {
    u64 d; asm("fma.rn.f32x2 %0, %1, %2, %3;" : "=l"(d) : "l"(a), "l"(b), "l"(c));
    return d;
}

// ---------------- router: logits, top-2, softmax over the pair --------------
__global__ void router_kernel(const float* __restrict__ x,
                              const float* __restrict__ wg) {
    int warp = (blockIdx.x * blockDim.x + threadIdx.x) >> 5;
    int lane = threadIdx.x & 31;
    if (warp >= Tn) return;

    const float4* x4 = (const float4*)(x + (size_t)warp * Dm);
    float acc[NE];
#pragma unroll
    for (int e = 0; e < NE; e++) acc[e] = 0.f;

#pragma unroll
    for (int i = 0; i < Dm / 4 / 32; i++) {       // 8 iterations
        float4 v = x4[lane + i * 32];
        int k0 = (lane + i * 32) * 4;
#pragma unroll
        for (int j = 0; j < 4; j++) {
            float xv = (j == 0) ? v.x : (j == 1) ? v.y : (j == 2) ? v.z : v.w;
            float4 wA = *(const float4*)(wg + (size_t)(k0 + j) * NE);
            float4 wB = *(const float4*)(wg + (size_t)(k0 + j) * NE + 4);
            acc[0] += xv * wA.x; acc[1] += xv * wA.y;
            acc[2] += xv * wA.z; acc[3] += xv * wA.w;
            acc[4] += xv * wB.x; acc[5] += xv * wB.y;
            acc[6] += xv * wB.z; acc[7] += xv * wB.w;
        }
    }
#pragma unroll
    for (int off = 16; off; off >>= 1)
#pragma unroll
        for (int e = 0; e < NE; e++)
            acc[e] += __shfl_xor_sync(0xffffffffu, acc[e], off);

    if (lane == 0) {
        int   b0 = 0;  float v0 = acc[0];
        for (int e = 1; e < NE; e++) if (acc[e] > v0) { v0 = acc[e]; b0 = e; }
        int   b1 = -1; float v1 = -INFINITY;
        for (int e = 0; e < NE; e++) if (e != b0 && acc[e] > v1) { v1 = acc[e]; b1 = e; }
        float e1 = expf(v1 - v0);        // v0 >= v1
        float inv = 1.0f / (1.0f + e1);
        g_e0[warp] = b0; g_e1[warp] = b1;
        g_w0[warp] = inv; g_w1[warp] = e1 * inv;
    }
}

// ---------------- exact cumsum ranking + capacity drop (1 warp / expert) ----
__global__ void assign_kernel() {
    int e    = threadIdx.x >> 5;
    int lane = threadIdx.x & 31;
    int base = 0;
    for (int i0 = 0; i0 < 2 * Tn; i0 += 32) {
        int idx = i0 + lane;
        int t   = idx & (Tn - 1);
        int sel = (idx < Tn) ? g_e0[t] : g_e1[t];
        bool mine = (sel == e);
        unsigned bal = __ballot_sync(0xffffffffu, mine);
        int pre = __popc(bal & ((1u << lane) - 1u));
        if (mine) {
            int slot = base + pre;
            int s = (slot < CAP) ? slot : -1;
            if (idx < Tn) g_s0[t] = s; else g_s1[t] = s;
            if (s >= 0) g_tok[e * CAP + s] = t;
        }
        base += __popc(bal);
    }
    int cnt = min(base, CAP);
    if (lane == 0) g_count[e] = cnt;
    for (int s = cnt + lane; s < CAP; s += 32) g_tok[e * CAP + s] = -1;
}

// ---------------- GEMM1: gather(x) @ c_fc[e]  -> gelu -> g_h -----------------
__global__ void __launch_bounds__(256)
gemm1_kernel(const float* __restrict__ x, const float* __restrict__ cfc) {
    const int e    = blockIdx.z;
    const int row0 = blockIdx.y * BM;
    if (row0 >= g_count[e]) return;          // skip empty capacity tiles
    const int nb = blockIdx.x * BN;

    __shared__ __align__(16) float As[BK][BM];
    __shared__ __align__(16) float Bs[BK][BN];

    const int tid = threadIdx.x;
    const int ar  = tid >> 2;
    const int ak  = (tid & 3) << 2;
    const int bkr = tid >> 5;
    const int bn  = (tid & 31) << 2;
    const int ty  = tid >> 4, tx = tid & 15;

    const int tokA = g_tok[e * CAP + row0 + ar];
    const int tokB = g_tok[e * CAP + row0 + ar + 64];
    const float* Bbase = cfc + (size_t)e * Dm * Hm + (size_t)bkr * Hm + nb + bn;

    u64 acc[8][4];
#pragma unroll
    for (int i = 0; i < 8; i++)
#pragma unroll
        for (int j = 0; j < 4; j++) acc[i][j] = 0ull;

    float4 a0 = make_float4(0, 0, 0, 0), a1 = a0, b0, b1;
    if (tokA >= 0) a0 = *(const float4*)(x + (size_t)tokA * Dm + ak);
    if (tokB >= 0) a1 = *(const float4*)(x + (size_t)tokB * Dm + ak);
    b0 = *(const float4*)(Bbase);
    b1 = *(const float4*)(Bbase + (size_t)8 * Hm);

    for (int k0 = 0; k0 < Dm; k0 += BK) {
        __syncthreads();
        As[ak + 0][ar] = a0.x; As[ak + 1][ar] = a0.y;
        As[ak + 2][ar] = a0.z; As[ak + 3][ar] = a0.w;
        As[ak + 0][ar + 64] = a1.x; As[ak + 1][ar + 64] = a1.y;
        As[ak + 2][ar + 64] = a1.z; As[ak + 3][ar + 64] = a1.w;
        *(float4*)&Bs[bkr][bn]     = b0;
        *(float4*)&Bs[bkr + 8][bn] = b1;
        __syncthreads();

        int kn = k0 + BK;
        if (kn < Dm) {                                  // prefetch next tile
            a0 = make_float4(0, 0, 0, 0); a1 = a0;
            if (tokA >= 0) a0 = *(const float4*)(x + (size_t)tokA * Dm + kn + ak);
            if (tokB >= 0) a1 = *(const float4*)(x + (size_t)tokB * Dm + kn + ak);
            b0 = *(const float4*)(Bbase + (size_t)kn * Hm);
            b1 = *(const float4*)(Bbase + (size_t)(kn + 8) * Hm);
        }
#pragma unroll
        for (int kk = 0; kk < BK; kk++) {
            float4 aA = *(const float4*)&As[kk][ty * 8];
            float4 aB = *(const float4*)&As[kk][ty * 8 + 4];
            ulonglong2 bA = *(const ulonglong2*)&Bs[kk][tx * 8];
            ulonglong2 bB = *(const ulonglong2*)&Bs[kk][tx * 8 + 4];
            u64 b2[4] = { bA.x, bA.y, bB.x, bB.y };
            float av[8] = { aA.x, aA.y, aA.z, aA.w, aB.x, aB.y, aB.z, aB.w };
#pragma unroll
            for (int i = 0; i < 8; i++) {
                u64 a2 = pack2(av[i], av[i]);
#pragma unroll
                for (int j = 0; j < 4; j++) acc[i][j] = fma2(a2, b2[j], acc[i][j]);
            }
        }
    }

#pragma unroll
    for (int i = 0; i < 8; i++) {
        float v[8];
#pragma unroll
        for (int j = 0; j < 4; j++) unpack2(acc[i][j], v[2 * j], v[2 * j + 1]);
#pragma unroll
        for (int j = 0; j < 8; j++) {
            float t = v[j];
            v[j] = 0.5f * t * (1.0f + erff(t * 0.70710678118654752440f));
        }
        float* p = g_h + (size_t)(e * CAP + row0 + ty * 8 + i) * Hm + nb + tx * 8;
        *(float4*)p       = make_float4(v[0], v[1], v[2], v[3]);
        *(float4*)(p + 4) = make_float4(v[4], v[5], v[6], v[7]);
    }
}

// ---------------- GEMM2: g_h @ c_proj[e] -> g_eo -----------------------------
__global__ void __launch_bounds__(256)
gemm2_kernel(const float* __restrict__ cproj) {
    const int e    = blockIdx.z;
    const int row0 = blockIdx.y * BM;
    if (row0 >= g_count[e]) return;
    const int nb = blockIdx.x * BN;

    __shared__ __align__(16) float As[BK][BM];
    __shared__ __align__(16) float Bs[BK][BN];

    const int tid = threadIdx.x;
    const int ar  = tid >> 2;
    const int ak  = (tid & 3) << 2;
    const int bkr = tid >> 5;
    const int bn  = (tid & 31) << 2;
    const int ty  = tid >> 4, tx = tid & 15;

    const float* Arow0 = g_h + (size_t)(e * CAP + row0 + ar) * Hm + ak;
    const float* Arow1 = Arow0 + (size_t)64 * Hm;
    const float* Bbase = cproj + (size_t)e * Hm * Dm + (size_t)bkr * Dm + nb + bn;

    u64 acc[8][4];
#pragma unroll
    for (int i = 0; i < 8; i++)
#pragma unroll
        for (int j = 0; j < 4; j++) acc[i][j] = 0ull;

    float4 a0 = *(const float4*)(Arow0);
    float4 a1 = *(const float4*)(Arow1);
    float4 b0 = *(const float4*)(Bbase);
    float4 b1 = *(const float4*)(Bbase + (size_t)8 * Dm);

    for (int k0 = 0; k0 < Hm; k0 += BK) {
        __syncthreads();
        As[ak + 0][ar] = a0.x; As[ak + 1][ar] = a0.y;
        As[ak + 2][ar] = a0.z; As[ak + 3][ar] = a0.w;
        As[ak + 0][ar + 64] = a1.x; As[ak + 1][ar + 64] = a1.y;
        As[ak + 2][ar + 64] = a1.z; As[ak + 3][ar + 64] = a1.w;
        *(float4*)&Bs[bkr][bn]     = b0;
        *(float4*)&Bs[bkr + 8][bn] = b1;
        __syncthreads();

        int kn = k0 + BK;
        if (kn < Hm) {
            a0 = *(const float4*)(Arow0 + kn);
            a1 = *(const float4*)(Arow1 + kn);
            b0 = *(const float4*)(Bbase + (size_t)kn * Dm);
            b1 = *(const float4*)(Bbase + (size_t)(kn + 8) * Dm);
        }
#pragma unroll
        for (int kk = 0; kk < BK; kk++) {
            float4 aA = *(const float4*)&As[kk][ty * 8];
            float4 aB = *(const float4*)&As[kk][ty * 8 + 4];
            ulonglong2 bA = *(const ulonglong2*)&Bs[kk][tx * 8];
            ulonglong2 bB = *(const ulonglong2*)&Bs[kk][tx * 8 + 4];
            u64 b2[4] = { bA.x, bA.y, bB.x, bB.y };
            float av[8] = { aA.x, aA.y, aA.z, aA.w, aB.x, aB.y, aB.z, aB.w };
#pragma unroll
            for (int i = 0; i < 8; i++) {
                u64 a2 = pack2(av[i], av[i]);
#pragma unroll
                for (int j = 0; j < 4; j++) acc[i][j] = fma2(a2, b2[j], acc[i][j]);
            }
        }
    }

#pragma unroll
    for (int i = 0; i < 8; i++) {
        float v[8];
#pragma unroll
        for (int j = 0; j < 4; j++) unpack2(acc[i][j], v[2 * j], v[2 * j + 1]);
        float* p = g_eo + (size_t)(e * CAP + row0 + ty * 8 + i) * Dm + nb + tx * 8;
        *(float4*)p       = make_float4(v[0], v[1], v[2], v[3]);
        *(float4*)(p + 4) = make_float4(v[4], v[5], v[6], v[7]);
    }
}

// ---------------- combine: out[t] = w0*eo[e0,s0] + w1*eo[e1,s1] --------------
__global__ void combine_kernel(float* __restrict__ out) {
    int t = blockIdx.x;
    int c = threadIdx.x * 4;
    int e0 = g_e0[t], e1 = g_e1[t];
    int s0 = g_s0[t], s1 = g_s1[t];
    float w0 = g_w0[t], w1 = g_w1[t];
    float4 r = make_float4(0, 0, 0, 0);
    if (s0 >= 0) {
        float4 v = *(const float4*)(g_eo + (size_t)(e0 * CAP + s0) * Dm + c);
        r.x += w0 * v.x; r.y += w0 * v.y; r.z += w0 * v.z; r.w += w0 * v.w;
    }
    if (s1 >= 0) {
        float4 v = *(const float4*)(g_eo + (size_t)(e1 * CAP + s1) * Dm + c);
        r.x += w1 * v.x; r.y += w1 * v.y; r.z += w1 * v.z; r.w += w1 * v.w;
    }
    *(float4*)(out + (size_t)t * Dm + c) = r;
}

// ---------------- launch -----------------------------------------------------
extern "C" void kernel_launch(void* const* d_in, const int* in_sizes, int n_in,
                              void* d_out, int out_size) {
    const float* x     = (const float*)d_in[0];
    const float* wg    = (const float*)d_in[1];
    const float* cfc   = (const float*)d_in[2];
    const float* cproj = (const float*)d_in[3];
    float* out = (float*)d_out;

    router_kernel<<<Tn / 8, 256>>>(x, wg);      // 8 warps/block, 1 warp/token
    assign_kernel<<<1, 256>>>();
    gemm1_kernel<<<dim3(Hm / BN, CAP / BM, NE), 256>>>(x, cfc);
    gemm2_kernel<<<dim3(Dm / BN, CAP / BM, NE), 256>>>(cproj);
    combine_kernel<<<Tn, 256>>>(out);
}